// round 17
// baseline (speedup 1.0000x reference)
#include <cuda_runtime.h>
#include <cuda_fp16.h>

#define PATCH_NUM 16
#define RPE_NUM   33          // 2*PATCH_NUM + 1
#define NUM_HEADS 8
#define GH        48
#define GW        48
#define NPIX      2304        // 48*48
#define NB        2
#define TAB_ROWS  (3 * RPE_NUM)   // 99
#define NI        4               // query pixels per tile (one head-half)
#define NCOPY     16              // smem replication copies
#define NSM       148
#define PBLOCKS   (2 * NSM)       // persistent blocks: 2 per SM
#define NTILES    ((NPIX / NI) * 2 * NB)   // 576 * 2 * 2 = 2304

// Scratch for normalized depth (allocation-free: __device__ global).
__device__ __align__(16) float g_znorm[NB * NPIX];

// ---------------------------------------------------------------------------
// Kernel 1: per-image min/max + normalization. One block per image,
// 288 threads x 2 float4 loads each (2304 floats), float4 stores.
// ---------------------------------------------------------------------------
__global__ __launch_bounds__(288) void minmax_norm_kernel(
    const float* __restrict__ depth)
{
    const int b = blockIdx.x;
    const float4* d4p = reinterpret_cast<const float4*>(depth + b * NPIX);
    __shared__ float s_mn[9], s_mx[9];
    const int tid = threadIdx.x;   // 288 threads -> 9 warps

    const float4 a = d4p[tid];
    const float4 c = d4p[tid + 288];

    float mn = fminf(fminf(fminf(a.x, a.y), fminf(a.z, a.w)),
                     fminf(fminf(c.x, c.y), fminf(c.z, c.w)));
    float mx = fmaxf(fmaxf(fmaxf(a.x, a.y), fmaxf(a.z, a.w)),
                     fmaxf(fmaxf(c.x, c.y), fmaxf(c.z, c.w)));
#pragma unroll
    for (int o = 16; o > 0; o >>= 1) {
        mn = fminf(mn, __shfl_xor_sync(0xffffffffu, mn, o));
        mx = fmaxf(mx, __shfl_xor_sync(0xffffffffu, mx, o));
    }
    if ((tid & 31) == 0) { s_mn[tid >> 5] = mn; s_mx[tid >> 5] = mx; }
    __syncthreads();
    if (tid < 32) {
        mn = (tid < 9) ? s_mn[tid] : 3.4e38f;
        mx = (tid < 9) ? s_mx[tid] : -3.4e38f;
#pragma unroll
        for (int o = 8; o > 0; o >>= 1) {
            mn = fminf(mn, __shfl_xor_sync(0xffffffffu, mn, o));
            mx = fmaxf(mx, __shfl_xor_sync(0xffffffffu, mx, o));
        }
        if (tid == 0) { s_mn[0] = mn; s_mx[0] = (mx - mn) + 1e-8f; }
    }
    __syncthreads();
    const float zmn   = s_mn[0];
    const float denom = s_mx[0];

    float4* zp = reinterpret_cast<float4*>(g_znorm + b * NPIX);
    zp[tid] = make_float4((a.x - zmn) / denom, (a.y - zmn) / denom,
                          (a.z - zmn) / denom, (a.w - zmn) / denom);
    zp[tid + 288] = make_float4((c.x - zmn) / denom, (c.y - zmn) / denom,
                                (c.z - zmn) / denom, (c.w - zmn) / denom);
}

// ---------------------------------------------------------------------------
// Kernel 2: PERSISTENT. 296 blocks (2/SM), each loops over tiles
// t = bid, bid+296, ... Each tile = (b, half, i-quad): 4 query pixels x
// one table half, identical per-tile work and 36KB-contiguous write
// granularity to the proven best configuration. Table prologue paid ONCE
// per block; no wave transitions.
//
// Tile decode: t in [0, 2304): b = t / 1152, half = (t / 576) & 1,
// iq = t % 576. Consecutive t for one block (stride 296) stays within one
// (b, half) group for ~2 iterations of the loop at most before b changes;
// zj4 is reloaded only when b changes.
//
// Table half in smem as fp16, replicated 16x, 128B row stride -> all
// gathers conflict-free. fp32 adds in reference association order.
// ---------------------------------------------------------------------------
__global__ __launch_bounds__(576, 2) void rpe_kernel(
    const float4* __restrict__ table4, float* __restrict__ out)
{
    __shared__ __align__(128) uint2 s_tab[2][TAB_ROWS][NCOPY];  // 25344 B

    const int tid = threadIdx.x;
    const int bid = blockIdx.x;

    // Prologue ONCE: both table halves, fp16-convert + replicate.
    for (int e = tid; e < 2 * TAB_ROWS; e += 576) {
        const int half = (e >= TAB_ROWS) ? 1 : 0;
        const int row  = e - half * TAB_ROWS;
        const float4 f = __ldg(&table4[row * 2 + half]);
        const __half2 a  = __floats2half2_rn(f.x, f.y);
        const __half2 bb = __floats2half2_rn(f.z, f.w);
        uint2 p;
        p.x = *reinterpret_cast<const unsigned int*>(&a);
        p.y = *reinterpret_cast<const unsigned int*>(&bb);
#pragma unroll
        for (int cpw = 0; cpw < NCOPY; ++cpw) s_tab[half][row][cpw] = p;
    }
    __syncthreads();

    const int cp  = tid & (NCOPY - 1);       // replication copy for this lane
    const int j0  = tid * 4;                 // 576*4 == 2304 == NPIX
    const int rj  = j0 / GW;
    const int cj0 = j0 - rj * GW;            // 4 j's share a pixel row

    const float XY_SCALE = 16.0f / 47.0f;
    const size_t plane = (size_t)NPIX * NPIX;

    float zjv[4];
    int cur_b = -1;

    for (int t = bid; t < NTILES; t += PBLOCKS) {
        const int b    = t / (2 * (NPIX / NI));          // t / 1152
        const int rem  = t - b * (2 * (NPIX / NI));
        const int half = rem / (NPIX / NI);              // table half
        const int iq   = rem - half * (NPIX / NI);
        const int i0   = iq * NI;

        if (b != cur_b) {
            const float4 zj4 =
                *reinterpret_cast<const float4*>(&g_znorm[b * NPIX + j0]);
            zjv[0] = zj4.x; zjv[1] = zj4.y; zjv[2] = zj4.z; zjv[3] = zj4.w;
            cur_b = b;
        }

#pragma unroll 1
        for (int ii = 0; ii < NI; ++ii) {
            const int i  = i0 + ii;
            const int ri = i / GW;
            const int ci = i - ri * GW;
            const float zi = __ldg(&g_znorm[b * NPIX + i]);

            float qy = rintf((float)(ri - rj) * XY_SCALE);
            qy = fminf(fmaxf(qy, -16.0f), 16.0f);
            const int iy = (int)qy + PATCH_NUM + RPE_NUM;

            int ixv[4], izv[4];
#pragma unroll
            for (int k = 0; k < 4; ++k) {
                float qx = rintf((float)(ci - (cj0 + k)) * XY_SCALE);
                qx = fminf(fmaxf(qx, -16.0f), 16.0f);
                ixv[k] = (int)qx + PATCH_NUM;

                float qz = rintf((zi - zjv[k]) * 16.0f);
                qz = fminf(fmaxf(qz, -16.0f), 16.0f);
                izv[k] = (int)qz + PATCH_NUM + 2 * RPE_NUM;
            }

            const uint2 tyu = s_tab[half][iy][cp];
            const float2 tya = __half22float2(*reinterpret_cast<const __half2*>(&tyu.x));
            const float2 tyb = __half22float2(*reinterpret_cast<const __half2*>(&tyu.y));

            float r0[4], r1[4], r2[4], r3[4];
#pragma unroll
            for (int k = 0; k < 4; ++k) {
                const uint2 txu = s_tab[half][ixv[k]][cp];
                const uint2 tzu = s_tab[half][izv[k]][cp];
                const float2 txa = __half22float2(*reinterpret_cast<const __half2*>(&txu.x));
                const float2 txb = __half22float2(*reinterpret_cast<const __half2*>(&txu.y));
                const float2 tza = __half22float2(*reinterpret_cast<const __half2*>(&tzu.x));
                const float2 tzb = __half22float2(*reinterpret_cast<const __half2*>(&tzu.y));
                // match reference sum order: (x + y) + z  (fp32 adds)
                r0[k] = (txa.x + tya.x) + tza.x;
                r1[k] = (txa.y + tya.y) + tza.y;
                r2[k] = (txb.x + tyb.x) + tzb.x;
                r3[k] = (txb.y + tyb.y) + tzb.y;
            }

            const size_t base =
                ((size_t)(b * NUM_HEADS + half * 4) * NPIX + (size_t)i) * NPIX + j0;
            __stcs(reinterpret_cast<float4*>(out + base + 0 * plane),
                   make_float4(r0[0], r0[1], r0[2], r0[3]));
            __stcs(reinterpret_cast<float4*>(out + base + 1 * plane),
                   make_float4(r1[0], r1[1], r1[2], r1[3]));
            __stcs(reinterpret_cast<float4*>(out + base + 2 * plane),
                   make_float4(r2[0], r2[1], r2[2], r2[3]));
            __stcs(reinterpret_cast<float4*>(out + base + 3 * plane),
                   make_float4(r3[0], r3[1], r3[2], r3[3]));
        }
    }
}

// ---------------------------------------------------------------------------
extern "C" void kernel_launch(void* const* d_in, const int* in_sizes, int n_in,
                              void* d_out, int out_size) {
    const float*  depth = (const float*)d_in[0];     // (2,48,48) f32
    const float4* table = (const float4*)d_in[1];    // (99,8) f32 -> 198 float4
    float* out = (float*)d_out;                      // (2,8,2304,2304) f32

    minmax_norm_kernel<<<NB, 288>>>(depth);

    rpe_kernel<<<PBLOCKS, 576>>>(table, out);
}